// round 8
// baseline (speedup 1.0000x reference)
#include <cuda_runtime.h>
#include <cuda_bf16.h>
#include <math_constants.h>

#define KNN 32
#define NPB 128            // atoms per molecule (contiguous, 128-aligned)
#define NPW 2              // nodes per warp: node0 -> ALU flavor, node1 -> FP flavor
#define WARPS_PER_CTA 4
#define NODES_PER_CTA (NPW * WARPS_PER_CTA)  // 8
typedef unsigned int u32;

// ---------------- Key flavors ----------------
// Both implement the same total order as jax.lax.top_k(-masked):
// (d2 ascending, index ascending). Pads carry key=+max and payload=self, so
// the epilogue needs no pad branch (pads are mutually bit-identical).

// ALU-pipe flavor: (u32 d2bits, u32 idx), lexicographic ISETP compare.
// d2 >= 0 so float order == unsigned-bit order. d2bits <= 0x41C80000 < pad.
struct KeyI {
  u32 k, j;
  __device__ __forceinline__ static KeyI make(bool ok, float d2, int j,
                                              int self) {
    KeyI r;
    r.k = ok ? __float_as_uint(d2) : 0x7FFFFFFFu;
    r.j = ok ? (u32)j : (u32)self;
    return r;
  }
  __device__ __forceinline__ bool less(const KeyI& o) const {
    return (k < o.k) || ((k == o.k) && (j < o.j));
  }
  __device__ __forceinline__ KeyI shfl(int m) const {
    KeyI r;
    r.k = __shfl_xor_sync(0xFFFFFFFFu, k, m);
    r.j = __shfl_xor_sync(0xFFFFFFFFu, j, m);
    return r;
  }
  __device__ __forceinline__ int idx() const { return (int)j; }
};

// FP-pipe flavor: (float d2, float idx), lexicographic FSETP/FSEL compare.
struct KeyF {
  float f, i;
  __device__ __forceinline__ static KeyF make(bool ok, float d2, int j,
                                              int self) {
    KeyF r;
    r.f = ok ? d2 : CUDART_INF_F;
    r.i = ok ? (float)j : (float)self;
    return r;
  }
  __device__ __forceinline__ bool less(const KeyF& o) const {
    return (f < o.f) || ((f == o.f) && (i < o.i));
  }
  __device__ __forceinline__ KeyF shfl(int m) const {
    KeyF r;
    r.f = __shfl_xor_sync(0xFFFFFFFFu, f, m);
    r.i = __shfl_xor_sync(0xFFFFFFFFu, i, m);
    return r;
  }
  __device__ __forceinline__ int idx() const { return (int)i; }
};

// ---------------- Network primitives ----------------
template <class K>
__device__ __forceinline__ void cas(K& a, int m, bool keepMin) {
  K o = a.shfl(m);
  const bool lt = a.less(o);
  a = (lt == keepMin) ? a : o;
}

template <bool ASC, class K>
__device__ __forceinline__ void sort32(K& a, int lane) {
#pragma unroll
  for (int k = 2; k <= 32; k <<= 1) {
#pragma unroll
    for (int j = k >> 1; j > 0; j >>= 1) {
      const bool base = (((lane & j) == 0) == ((lane & k) == 0));
      cas(a, j, base == ASC);
    }
  }
}

// a ascending, b descending -> 32 smallest of the 64, sorted (ASC or DESC).
// concat(asc, desc) is bitonic; elementwise min is its half-cleaner low half.
template <bool ASC, class K>
__device__ __forceinline__ K keep_low(K a_asc, K b_desc, int lane) {
  K t = a_asc.less(b_desc) ? a_asc : b_desc;
#pragma unroll
  for (int j = 16; j > 0; j >>= 1) {
    cas(t, j, ((lane & j) == 0) == ASC);
  }
  return t;
}

template <class K>
__device__ __forceinline__ K select_top32(K r0, K r1, K r2, K r3, int lane) {
  sort32<true>(r0, lane);
  sort32<false>(r1, lane);
  sort32<true>(r2, lane);
  sort32<false>(r3, lane);
  K t01 = keep_low<true>(r0, r1, lane);   // ascending
  K t23 = keep_low<false>(r2, r3, lane);  // descending
  return keep_low<true>(t01, t23, lane);  // ascending final
}

// d2 arithmetic replicates the reference's (XLA, contraction-on) rounding:
//   sq  = fma(z,z, fma(y,y, x*x))
//   dot = fma(z,z', fma(y,y', x*x'))
//   d2  = max((sq_i + sq_j) - 2*dot, 0)
template <class K>
__device__ __forceinline__ void process_node(
    int n, int molbase, int lane, const float* sx, const float* sy,
    const float* sz, const float* ssq, const int* sb, float* out,
    long long NK) {
  const int self = n & (NPB - 1);
  const float x = sx[self], y = sy[self], z = sz[self];
  const float sq = ssq[self];
  const int bme = sb[self];

  K r[4];
#pragma unroll
  for (int m = 0; m < 4; m++) {
    const int j = m * 32 + lane;
    const float dot =
        __fmaf_rn(z, sz[j], __fmaf_rn(y, sy[j], __fmul_rn(x, sx[j])));
    float d2 = __fsub_rn(__fadd_rn(sq, ssq[j]), __fmul_rn(2.0f, dot));
    d2 = fmaxf(d2, 0.0f);
    r[m] = K::make((sb[j] == bme) && (d2 <= 25.0f), d2, j, self);
  }

  const K key = select_top32(r[0], r[1], r[2], r[3], lane);

  const int j = key.idx();  // pads already carry self
  const float vx = x - sx[j];
  const float vy = y - sy[j];
  const float vz = z - sz[j];
  const float ssv = __fmaf_rn(vz, vz, __fmaf_rn(vy, vy, __fmul_rn(vx, vx)));
  const float w = (j == self) ? 0.0f : __fsqrt_rn(ssv);

  const int e = n * KNN + lane;
  out[e]          = (float)n;
  out[NK + e]     = (float)(molbase + j);
  out[2 * NK + e] = w;
  float* __restrict__ ov = out + 3 * NK + 3LL * e;
  ov[0] = vx; ov[1] = vy; ov[2] = vz;
}

__global__ __launch_bounds__(NPB) void radius_graph_kernel(
    const float* __restrict__ pos, const int* __restrict__ batch,
    float* __restrict__ out, int N) {
  __shared__ float sx[NPB], sy[NPB], sz[NPB], ssq[NPB];
  __shared__ int sb[NPB];

  const int tid  = threadIdx.x;
  const int lane = tid & 31;
  const int wid  = tid >> 5;
  const int nbase = blockIdx.x * NODES_PER_CTA;
  const int molbase = nbase & ~(NPB - 1);

  {
    const float ax = pos[3 * (molbase + tid) + 0];
    const float ay = pos[3 * (molbase + tid) + 1];
    const float az = pos[3 * (molbase + tid) + 2];
    sx[tid] = ax; sy[tid] = ay; sz[tid] = az;
    ssq[tid] = __fmaf_rn(az, az, __fmaf_rn(ay, ay, __fmul_rn(ax, ax)));
    sb[tid]  = batch[molbase + tid];
  }
  __syncthreads();

  const long long NK = (long long)N * KNN;
  const int n0 = nbase + wid * NPW;

  // Node 0 on the ALU pipe (int keys), node 1 on the FP pipe (float keys).
  process_node<KeyI>(n0 + 0, molbase, lane, sx, sy, sz, ssq, sb, out, NK);
  process_node<KeyF>(n0 + 1, molbase, lane, sx, sy, sz, ssq, sb, out, NK);
}

extern "C" void kernel_launch(void* const* d_in, const int* in_sizes, int n_in,
                              void* d_out, int out_size) {
  const float* pos  = (const float*)d_in[0];
  const int* batch  = (const int*)d_in[1];
  const int N = in_sizes[0] / 3;            // pos is [N,3]
  const int nblocks = N / NODES_PER_CTA;    // 8 nodes per CTA, 2 per warp
  radius_graph_kernel<<<nblocks, NPB>>>(pos, batch, (float*)d_out, N);
}

// round 9
// speedup vs baseline: 1.4333x; 1.4333x over previous
#include <cuda_runtime.h>
#include <cuda_bf16.h>

#define KNN 32
#define NPB 128            // atoms per molecule (contiguous, 128-aligned)
#define WARPS_PER_CTA 4
#define NODES_PER_CTA 4    // one node per warp
typedef unsigned long long u64;
typedef unsigned int u32;

// Pad key: high word 0x7FFFFFFF (> any d2bits, which is <= 0x41C80000 for
// d2 <= 25), low word = self index. All pads of a node are bit-identical, so
// their arbitrary relative order is harmless, and the epilogue can read the
// neighbor index straight from the low word with no pad branch.

__device__ __forceinline__ u64 shflx64(u64 v, int m) {
  // Compiler splits into two 32-bit SHFL.BFLY.
  return __shfl_xor_sync(0xFFFFFFFFu, v, m);
}

// One compare-exchange step of a bitonic network on u64 keys.
__device__ __forceinline__ void cas64(u64& a, int m, bool keepMin) {
  const u64 o = shflx64(a, m);
  const bool lt = a < o;           // ISETP.U32 + ISETP.X  (2 instrs)
  a = (lt == keepMin) ? a : o;     // 2 SEL
}

// Full 32-element bitonic sort across the warp, direction by template.
template <bool ASC>
__device__ __forceinline__ void sort32(u64& a, int lane) {
#pragma unroll
  for (int k = 2; k <= 32; k <<= 1) {
#pragma unroll
    for (int j = k >> 1; j > 0; j >>= 1) {
      const bool base = (((lane & j) == 0) == ((lane & k) == 0));
      cas64(a, j, base == ASC);
    }
  }
}

// a sorted ascending, b sorted descending: concat is bitonic, so the
// elementwise min is the half-cleaner's low half = the 32 smallest (bitonic);
// a 5-stage bitonic merge then sorts it ASC or DESC. No reverse shuffle.
template <bool ASC>
__device__ __forceinline__ u64 keep_low(u64 a_asc, u64 b_desc, int lane) {
  u64 t = (a_asc < b_desc) ? a_asc : b_desc;
#pragma unroll
  for (int j = 16; j > 0; j >>= 1) {
    cas64(t, j, ((lane & j) == 0) == ASC);
  }
  return t;
}

// Warp-per-node radius graph; exact top-32 (d2 asc, idx asc) like
// jax.lax.top_k(-masked). d2 replicates the reference's (XLA contraction-on)
// rounding:
//   sq  = fma(z,z, fma(y,y, x*x))
//   dot = fma(z,z', fma(y,y', x*x'))
//   d2  = max((sq_i + sq_j) - 2*dot, 0)
__global__ __launch_bounds__(NPB) void radius_graph_kernel(
    const float* __restrict__ pos, const int* __restrict__ batch,
    float* __restrict__ out, int N) {
  __shared__ float sx[NPB], sy[NPB], sz[NPB], ssq[NPB];
  __shared__ int sb[NPB];

  const int tid  = threadIdx.x;
  const int lane = tid & 31;
  const int wid  = tid >> 5;
  const int n    = blockIdx.x * NODES_PER_CTA + wid;
  const int molbase = n & ~(NPB - 1);

  // Stage the molecule's 128 atoms (one per thread).
  {
    const float ax = pos[3 * (molbase + tid) + 0];
    const float ay = pos[3 * (molbase + tid) + 1];
    const float az = pos[3 * (molbase + tid) + 2];
    sx[tid] = ax; sy[tid] = ay; sz[tid] = az;
    ssq[tid] = __fmaf_rn(az, az, __fmaf_rn(ay, ay, __fmul_rn(ax, ax)));
    sb[tid]  = batch[molbase + tid];
  }
  __syncthreads();

  const int self = n & (NPB - 1);
  const float x = sx[self], y = sy[self], z = sz[self];
  const float sq = ssq[self];
  const int bme = sb[self];
  const u64 padkey = (0x7FFFFFFFULL << 32) | (u32)self;

  // Candidate keys: column m holds j = m*32 + lane.
  u64 r0, r1, r2, r3;
  {
    u64 rr[4];
#pragma unroll
    for (int m = 0; m < 4; m++) {
      const int j = m * 32 + lane;
      const float dot =
          __fmaf_rn(z, sz[j], __fmaf_rn(y, sy[j], __fmul_rn(x, sx[j])));
      float d2 = __fsub_rn(__fadd_rn(sq, ssq[j]), __fmul_rn(2.0f, dot));
      d2 = fmaxf(d2, 0.0f);
      const bool ok = (sb[j] == bme) && (d2 <= 25.0f);
      rr[m] = ok ? (((u64)__float_as_uint(d2) << 32) | (u32)j) : padkey;
    }
    r0 = rr[0]; r1 = rr[1]; r2 = rr[2]; r3 = rr[3];
  }

  // Two asc + two desc sorts, then min-merge tournament (no reversals).
  sort32<true >(r0, lane);
  sort32<false>(r1, lane);
  sort32<true >(r2, lane);
  sort32<false>(r3, lane);
  const u64 t01 = keep_low<true >(r0, r1, lane);  // ascending
  const u64 t23 = keep_low<false>(r2, r3, lane);  // descending
  const u64 key = keep_low<true >(t01, t23, lane);  // ascending final

  // Emit slot `lane` of node n; pads already carry self in the low word.
  const int j = (int)(u32)key;
  const float vx = x - sx[j];
  const float vy = y - sy[j];
  const float vz = z - sz[j];
  const float ssv = __fmaf_rn(vz, vz, __fmaf_rn(vy, vy, __fmul_rn(vx, vx)));
  const float w = (j == self) ? 0.0f : __fsqrt_rn(ssv);

  const long long NK = (long long)N * KNN;
  const int e = n * KNN + lane;
  out[e]          = (float)n;
  out[NK + e]     = (float)(molbase + j);
  out[2 * NK + e] = w;
  float* __restrict__ ov = out + 3 * NK + 3LL * e;
  ov[0] = vx; ov[1] = vy; ov[2] = vz;
}

extern "C" void kernel_launch(void* const* d_in, const int* in_sizes, int n_in,
                              void* d_out, int out_size) {
  const float* pos  = (const float*)d_in[0];
  const int* batch  = (const int*)d_in[1];
  const int N = in_sizes[0] / 3;            // pos is [N,3]
  const int nblocks = N / NODES_PER_CTA;    // one warp per node
  radius_graph_kernel<<<nblocks, NPB>>>(pos, batch, (float*)d_out, N);
}

// round 10
// speedup vs baseline: 1.5278x; 1.0660x over previous
#include <cuda_runtime.h>
#include <cuda_bf16.h>

#define KNN 32
#define NPB 128            // atoms per molecule (contiguous, 128-aligned)
#define NODES_PER_CTA 4    // one node per warp
typedef unsigned long long u64;
typedef unsigned int u32;

// Pad key: high word 0x7FFFFFFF (> any d2bits <= 0x41C80000 for d2<=25),
// low word = self index -> branch-free epilogue, exact top_k order preserved.

__device__ __forceinline__ u64 shflx64(u64 v, int m) {
  return __shfl_xor_sync(0xFFFFFFFFu, v, m);  // 2x 32-bit SHFL.BFLY
}

// One compare-exchange step of a bitonic network on u64 keys.
__device__ __forceinline__ void cas64(u64& a, int m, bool keepMin) {
  const u64 o = shflx64(a, m);
  const bool lt = a < o;           // ISETP.U32 + ISETP.X
  a = (lt == keepMin) ? a : o;     // 2x SEL
}

// Warp-per-node radius graph; exact sorted top-32 (d2 asc, idx asc), matching
// jax.lax.top_k(-masked). d2 replicates the reference's (XLA contraction-on)
// rounding:
//   sq  = fma(z,z, fma(y,y, x*x))
//   dot = fma(z,z', fma(y,y', x*x'))
//   d2  = max((sq_i + sq_j) - 2*dot, 0)
//
// The four 32-element column sorts are data-independent; they are textually
// interleaved stage-by-stage (4-way ILP) to hide the 26-cycle SHFL latency,
// and launch bounds allow 64 regs so all four chains stay in flight.
__global__ __launch_bounds__(NPB, 8) void radius_graph_kernel(
    const float* __restrict__ pos, const int* __restrict__ batch,
    float* __restrict__ out, int N) {
  __shared__ float sx[NPB], sy[NPB], sz[NPB], ssq[NPB];
  __shared__ int sb[NPB];

  const int tid  = threadIdx.x;
  const int lane = tid & 31;
  const int wid  = tid >> 5;
  const int n    = blockIdx.x * NODES_PER_CTA + wid;
  const int molbase = n & ~(NPB - 1);

  // Stage the molecule's 128 atoms (one per thread).
  {
    const float ax = pos[3 * (molbase + tid) + 0];
    const float ay = pos[3 * (molbase + tid) + 1];
    const float az = pos[3 * (molbase + tid) + 2];
    sx[tid] = ax; sy[tid] = ay; sz[tid] = az;
    ssq[tid] = __fmaf_rn(az, az, __fmaf_rn(ay, ay, __fmul_rn(ax, ax)));
    sb[tid]  = batch[molbase + tid];
  }
  __syncthreads();

  const int self = n & (NPB - 1);
  const float x = sx[self], y = sy[self], z = sz[self];
  const float sq = ssq[self];
  const int bme = sb[self];
  const u64 padkey = (0x7FFFFFFFULL << 32) | (u32)self;

  // Candidate keys: column m holds j = m*32 + lane.
  u64 r0, r1, r2, r3;
  {
    u64 rr[4];
#pragma unroll
    for (int m = 0; m < 4; m++) {
      const int j = m * 32 + lane;
      const float dot =
          __fmaf_rn(z, sz[j], __fmaf_rn(y, sy[j], __fmul_rn(x, sx[j])));
      float d2 = __fsub_rn(__fadd_rn(sq, ssq[j]), __fmul_rn(2.0f, dot));
      d2 = fmaxf(d2, 0.0f);
      const bool ok = (sb[j] == bme) && (d2 <= 25.0f);
      rr[m] = ok ? (((u64)__float_as_uint(d2) << 32) | (u32)j) : padkey;
    }
    r0 = rr[0]; r1 = rr[1]; r2 = rr[2]; r3 = rr[3];
  }

  // Four interleaved bitonic sorts: r0,r2 ascending; r1,r3 descending.
#pragma unroll
  for (int k = 2; k <= 32; k <<= 1) {
#pragma unroll
    for (int j = k >> 1; j > 0; j >>= 1) {
      const bool base = (((lane & j) == 0) == ((lane & k) == 0));
      cas64(r0, j, base);
      cas64(r1, j, !base);
      cas64(r2, j, base);
      cas64(r3, j, !base);
    }
  }

  // keep-low merges: concat(asc, desc) is bitonic -> elementwise min is the
  // 32 smallest; 5-stage merge sorts it. t01 ascending, t23 descending
  // (so the final merge also starts with a plain min). Interleaved 2-way.
  u64 t01 = (r0 < r1) ? r0 : r1;
  u64 t23 = (r2 < r3) ? r2 : r3;
#pragma unroll
  for (int j = 16; j > 0; j >>= 1) {
    const bool up = (lane & j) == 0;
    cas64(t01, j, up);    // ascending
    cas64(t23, j, !up);   // descending
  }
  u64 key = (t01 < t23) ? t01 : t23;
#pragma unroll
  for (int j = 16; j > 0; j >>= 1) {
    cas64(key, j, (lane & j) == 0);  // ascending final
  }

  // Emit slot `lane` of node n; pads already carry self in the low word.
  const int j = (int)(u32)key;
  const float vx = x - sx[j];
  const float vy = y - sy[j];
  const float vz = z - sz[j];
  const float ssv = __fmaf_rn(vz, vz, __fmaf_rn(vy, vy, __fmul_rn(vx, vx)));
  const float w = (j == self) ? 0.0f : __fsqrt_rn(ssv);

  const long long NK = (long long)N * KNN;
  const int e = n * KNN + lane;
  out[e]          = (float)n;
  out[NK + e]     = (float)(molbase + j);
  out[2 * NK + e] = w;
  float* __restrict__ ov = out + 3 * NK + 3LL * e;
  ov[0] = vx; ov[1] = vy; ov[2] = vz;
}

extern "C" void kernel_launch(void* const* d_in, const int* in_sizes, int n_in,
                              void* d_out, int out_size) {
  const float* pos  = (const float*)d_in[0];
  const int* batch  = (const int*)d_in[1];
  const int N = in_sizes[0] / 3;            // pos is [N,3]
  const int nblocks = N / NODES_PER_CTA;    // one warp per node
  radius_graph_kernel<<<nblocks, NPB>>>(pos, batch, (float*)d_out, N);
}